// round 15
// baseline (speedup 1.0000x reference)
#include <cuda_runtime.h>
#include <cuda_fp16.h>
#include <math.h>
#include <stdint.h>

#define THREADS 512
#define TM      256
#define KD      256
#define NN      64
#define KC      32
#define NCH     8
#define NWARP   16

#define BS      264              // fp16 per B row (256+8 pad) -> 528 B
#define AROW    144              // bytes per A row (32 fp32 + 4 pad)
#define AWBUF   (16 * AROW)      // 2304 B: one warp (16 rows), one buffer
#define AWREG   (2 * AWBUF)      // 4608 B per warp

// smem byte offsets
#define OFF_B1   0
#define OFF_B2   256
#define OFF_CW   272
#define OFF_SW   336
#define OFF_W2T  400             // 256 f -> ends 1424
#define OFF_B    1536            // 64*528 = 33792 -> ends 35328
#define OFF_A    35328           // 16 x 4608 = 73728 -> ends 109056
#define SMEM_BYTES 109056
// Hs overlay: per-warp own A region, 16 rows x 272 B = 4352 <= 4608

__device__ __forceinline__ void ldm_x4(uint32_t& r0, uint32_t& r1, uint32_t& r2, uint32_t& r3,
                                       uint32_t addr) {
    asm volatile("ldmatrix.sync.aligned.m8n8.x4.shared.b16 {%0,%1,%2,%3}, [%4];"
                 : "=r"(r0), "=r"(r1), "=r"(r2), "=r"(r3) : "r"(addr));
}
__device__ __forceinline__ void mma_f16(float* c, const uint32_t* a, uint32_t b0, uint32_t b1) {
    asm volatile("mma.sync.aligned.m16n8k16.row.col.f32.f16.f16.f32 "
                 "{%0,%1,%2,%3}, {%4,%5,%6,%7}, {%8,%9}, {%0,%1,%2,%3};"
                 : "+f"(c[0]), "+f"(c[1]), "+f"(c[2]), "+f"(c[3])
                 : "r"(a[0]), "r"(a[1]), "r"(a[2]), "r"(a[3]), "r"(b0), "r"(b1));
}
__device__ __forceinline__ uint32_t packh2(float x, float y) {
    __half2 h = __floats2half2_rn(x, y);
    return *(uint32_t*)&h;
}
__device__ __forceinline__ void cp_async16(uint32_t saddr, const void* gsrc) {
    asm volatile("cp.async.cg.shared.global [%0], [%1], 16;\n"
                 :: "r"(saddr), "l"(gsrc) : "memory");
}
__device__ __forceinline__ void cp_commit() {
    asm volatile("cp.async.commit_group;\n" ::: "memory");
}
template <int N>
__device__ __forceinline__ void cp_wait() {
    asm volatile("cp.async.wait_group %0;\n" :: "n"(N) : "memory");
}

extern "C" __global__ void __launch_bounds__(THREADS, 2)
qc_hmma10_kernel(const float* __restrict__ x,  const float* __restrict__ W1,
                 const float* __restrict__ b1, const float* __restrict__ W2,
                 const float* __restrict__ b2, const float* __restrict__ qw,
                 float* __restrict__ out)
{
    extern __shared__ char sm[];
    const uint32_t sb = (uint32_t)__cvta_generic_to_shared(sm);
    const int t   = threadIdx.x;
    const int wid = t >> 5;
    const int lid = t & 31;
    const long row0 = (long)blockIdx.x * TM;

    float* b1s = (float*)(sm + OFF_B1);
    float* b2s = (float*)(sm + OFF_B2);
    float* cw  = (float*)(sm + OFF_CW);
    float* sw  = (float*)(sm + OFF_SW);
    float* W2t = (float*)(sm + OFF_W2T);

    if (t < 64)  b1s[t] = b1[t];
    if (t < 4)   b2s[t] = b2[t];
    if (t < 16)  sincosf(0.5f * qw[t], &sw[t], &cw[t]);
    if (t < 256) { int j = t >> 6, q = t & 63; W2t[q * 4 + j] = W2[t]; }

    // ---- W1 -> smem fp16 [n][k], padded rows ----
    #pragma unroll
    for (int i = 0; i < 8; ++i) {
        int idx = t + i * THREADS;          // [0,4096) float4 slots
        int row = idx >> 6;
        int k4  = idx & 63;
        float4 v = *(const float4*)(W1 + row * KD + k4 * 4);
        uint32_t o = (uint32_t)row * (BS * 2) + (uint32_t)k4 * 8;
        *(uint2*)(sm + OFF_B + o) = make_uint2(packh2(v.x, v.y), packh2(v.z, v.w));
    }
    __syncthreads();   // barrier 1: B + tables visible

    // ---- per-warp async x pipeline: 16 rows per warp ----
    const uint32_t warpA = sb + OFF_A + (uint32_t)wid * AWREG;
    const float* xwarp = x + (row0 + wid * 16) * KD;
    auto cp_chunk = [&](int ch, int buf) {
        #pragma unroll
        for (int i = 0; i < 4; ++i) {
            int s   = lid + 32 * i;         // [0,128): 16 rows x 8 segs
            int r   = s >> 3;
            int seg = s & 7;
            cp_async16(warpA + (uint32_t)buf * AWBUF + (uint32_t)r * AROW + (uint32_t)seg * 16,
                       xwarp + r * KD + ch * KC + seg * 4);
        }
        cp_commit();
    };

    cp_chunk(0, 0);
    cp_chunk(1, 1);

    float acc[8][4];
    #pragma unroll
    for (int ni = 0; ni < 8; ++ni)
        #pragma unroll
        for (int c = 0; c < 4; ++c) acc[ni][c] = 0.0f;

    const uint32_t aTh = (uint32_t)(lid >> 2) * AROW + (uint32_t)(lid & 3) * 8;
    const uint32_t bBase = sb + OFF_B
        + ((((uint32_t)lid >> 4) << 3) + ((uint32_t)lid & 7)) * (BS * 2)
        + (((uint32_t)lid >> 3) & 1) * 16;

    for (int ch = 0; ch < NCH; ++ch) {
        if (ch < NCH - 1) cp_wait<1>(); else cp_wait<0>();
        __syncwarp();

        const int buf = ch & 1;
        const char* aB = sm + OFF_A + wid * AWREG + buf * AWBUF;

        #pragma unroll
        for (int ks = 0; ks < 2; ++ks) {
            const char* ap = aB + aTh + ks * 64;
            float2 f0 = *(const float2*)(ap);
            float2 f1 = *(const float2*)(ap + 8 * AROW);
            float2 f2 = *(const float2*)(ap + 32);
            float2 f3 = *(const float2*)(ap + 8 * AROW + 32);
            uint32_t a[4] = { packh2(f0.x, f0.y), packh2(f1.x, f1.y),
                              packh2(f2.x, f2.y), packh2(f3.x, f3.y) };

            const int it = ch * 2 + ks;
            uint32_t bf[4][4];
            #pragma unroll
            for (int g = 0; g < 4; ++g)
                ldm_x4(bf[g][0], bf[g][1], bf[g][2], bf[g][3],
                       bBase + (uint32_t)g * 16 * (BS * 2) + (uint32_t)it * 32);

            #pragma unroll
            for (int g = 0; g < 4; ++g) {
                mma_f16(acc[g * 2],     a, bf[g][0], bf[g][1]);
                mma_f16(acc[g * 2 + 1], a, bf[g][2], bf[g][3]);
            }
        }

        if (ch + 2 < NCH) cp_chunk(ch + 2, buf);
    }

    // ---- stage H into own warp's A region (own data; no barrier before write) ----
    {
        char* hw = sm + OFF_A + wid * AWREG;    // 16 rows x 272 B
        int rloc = lid >> 2;
        int col0 = (lid & 3) * 2;
        #pragma unroll
        for (int ni = 0; ni < 8; ++ni) {
            int col = ni * 8 + col0;
            float* r0p = (float*)(hw + rloc * 272);
            float* r1p = (float*)(hw + (rloc + 8) * 272);
            *(float2*)(r0p + col) = make_float2(acc[ni][0], acc[ni][1]);
            *(float2*)(r1p + col) = make_float2(acc[ni][2], acc[ni][3]);
        }
    }
    __syncthreads();   // barrier 2: Hs visible cross-warp

    // ---- per-row epilogue: threads 0-255, one row each ----
    if (t < TM) {
        const float* hrow = (const float*)(sm + OFF_A + (t >> 4) * AWREG + (t & 15) * 272);
        float ang0 = b2s[0], ang1 = b2s[1], ang2 = b2s[2], ang3 = b2s[3];
        #pragma unroll
        for (int q4 = 0; q4 < 16; ++q4) {
            float4 h4 = *(const float4*)(hrow + q4 * 4);
            float4 bb = *(const float4*)(b1s + q4 * 4);
            #pragma unroll
            for (int i = 0; i < 4; ++i) {
                float hv = (i == 0) ? h4.x : (i == 1) ? h4.y : (i == 2) ? h4.z : h4.w;
                float bv = (i == 0) ? bb.x : (i == 1) ? bb.y : (i == 2) ? bb.z : bb.w;
                float hq = fmaxf(hv + bv, 0.0f);
                float4 w = *(const float4*)(W2t + (q4 * 4 + i) * 4);
                ang0 += hq * w.x;  ang1 += hq * w.y;
                ang2 += hq * w.z;  ang3 += hq * w.w;
            }
        }
        float ang[4] = { tanhf(ang0), tanhf(ang1), tanhf(ang2), tanhf(ang3) };

        float sr[16], si[16];
        #pragma unroll
        for (int i = 0; i < 16; ++i) { sr[i] = 0.0f; si[i] = 0.0f; }
        sr[0] = 1.0f;

        #pragma unroll
        for (int w = 0; w < 4; ++w) {
            float c, s;
            __sincosf(0.5f * ang[w], &s, &c);
            const int m = 8 >> w;
            #pragma unroll
            for (int i0 = 0; i0 < 16; ++i0) if (!(i0 & m)) {
                const int i1 = i0 | m;
                float r0 = sr[i0], r1 = sr[i1];
                sr[i0] = c * r0 - s * r1;  sr[i1] = s * r0 + c * r1;
                float q0 = si[i0], q1 = si[i1];
                si[i0] = c * q0 - s * q1;  si[i1] = s * q0 + c * q1;
            }
        }

        #pragma unroll
        for (int l = 0; l < 2; ++l) {
            #pragma unroll
            for (int i = 0; i < 4; ++i) {
                {   // RY(weights[l,i,0])
                    const float c = cw[l * 8 + i * 2], s = sw[l * 8 + i * 2];
                    const int m = 8 >> i;
                    #pragma unroll
                    for (int i0 = 0; i0 < 16; ++i0) if (!(i0 & m)) {
                        const int i1 = i0 | m;
                        float r0 = sr[i0], r1 = sr[i1];
                        sr[i0] = c * r0 - s * r1;  sr[i1] = s * r0 + c * r1;
                        float q0 = si[i0], q1 = si[i1];
                        si[i0] = c * q0 - s * q1;  si[i1] = s * q0 + c * q1;
                    }
                }
                {   // RZ(weights[l,i,1])
                    const float c = cw[l * 8 + i * 2 + 1], s = sw[l * 8 + i * 2 + 1];
                    const int m = 8 >> i;
                    #pragma unroll
                    for (int idx = 0; idx < 16; ++idx) {
                        float re = sr[idx], im = si[idx];
                        if (idx & m) { sr[idx] = re * c - im * s;  si[idx] = im * c + re * s; }
                        else         { sr[idx] = re * c + im * s;  si[idx] = im * c - re * s; }
                    }
                }
            }
            #pragma unroll
            for (int cix = 0; cix < 4; ++cix) {
                const int ctrl = cix, tgt = (cix + 1) & 3;
                const int mc = 8 >> ctrl, mt = 8 >> tgt;
                #pragma unroll
                for (int idx = 0; idx < 16; ++idx)
                    if ((idx & mc) && !(idx & mt)) {
                        const int j2 = idx | mt;
                        float tr = sr[idx]; sr[idx] = sr[j2]; sr[j2] = tr;
                        float ti = si[idx]; si[idx] = si[j2]; si[j2] = ti;
                    }
            }
        }

        float z = 0.0f;
        #pragma unroll
        for (int idx = 0; idx < 16; ++idx) {
            float p = sr[idx] * sr[idx] + si[idx] * si[idx];
            z += (idx & 8) ? -p : p;
        }
        out[row0 + t] = z;
    }
}

extern "C" void kernel_launch(void* const* d_in, const int* in_sizes, int n_in,
                              void* d_out, int out_size) {
    const float* x  = (const float*)d_in[0];
    const float* W1 = (const float*)d_in[1];
    const float* b1 = (const float*)d_in[2];
    const float* W2 = (const float*)d_in[3];
    const float* b2 = (const float*)d_in[4];
    const float* qw = (const float*)d_in[5];
    float* out = (float*)d_out;

    const int B = in_sizes[0] / KD;   // 65536
    cudaFuncSetAttribute(qc_hmma10_kernel,
                         cudaFuncAttributeMaxDynamicSharedMemorySize, SMEM_BYTES);
    qc_hmma10_kernel<<<B / TM, THREADS, SMEM_BYTES>>>(x, W1, b1, W2, b2, qw, out);
}

// round 16
// speedup vs baseline: 1.0992x; 1.0992x over previous
#include <cuda_runtime.h>
#include <cuda_fp16.h>
#include <math.h>
#include <stdint.h>

#define THREADS 256
#define TM      256
#define KD      256
#define NN      64
#define KC      32
#define NCH     8

#define BS      264              // fp16 per B row (256+8 pad) -> 528 B
#define AROW    144              // bytes per A row (32 fp32 + 4 pad)
#define AWBUF   (32 * AROW)      // 4608 B: one warp (32 rows), one buffer
#define AWREG   (2 * AWBUF)      // 9216 B per warp

// smem byte offsets
#define OFF_B1   0
#define OFF_B2   256
#define OFF_CW   272
#define OFF_SW   336
#define OFF_W2T  400             // 256 f -> ends 1424
#define OFF_B    1536            // 64*528 = 33792 -> ends 35328
#define OFF_A    35328           // 8 x 9216 = 73728 -> ends 109056
#define SMEM_BYTES 109056
// Hs overlay: per-warp own A region: 32 rows x 272 B = 8704 <= 9216

__device__ __forceinline__ void ldm_x4(uint32_t& r0, uint32_t& r1, uint32_t& r2, uint32_t& r3,
                                       uint32_t addr) {
    asm volatile("ldmatrix.sync.aligned.m8n8.x4.shared.b16 {%0,%1,%2,%3}, [%4];"
                 : "=r"(r0), "=r"(r1), "=r"(r2), "=r"(r3) : "r"(addr));
}
__device__ __forceinline__ void mma_f16(float* c, const uint32_t* a, uint32_t b0, uint32_t b1) {
    asm volatile("mma.sync.aligned.m16n8k16.row.col.f32.f16.f16.f32 "
                 "{%0,%1,%2,%3}, {%4,%5,%6,%7}, {%8,%9}, {%0,%1,%2,%3};"
                 : "+f"(c[0]), "+f"(c[1]), "+f"(c[2]), "+f"(c[3])
                 : "r"(a[0]), "r"(a[1]), "r"(a[2]), "r"(a[3]), "r"(b0), "r"(b1));
}
__device__ __forceinline__ uint32_t packh2(float x, float y) {
    __half2 h = __floats2half2_rn(x, y);
    return *(uint32_t*)&h;
}
__device__ __forceinline__ void cp_async16(uint32_t saddr, const void* gsrc) {
    asm volatile("cp.async.cg.shared.global [%0], [%1], 16;\n"
                 :: "r"(saddr), "l"(gsrc) : "memory");
}
__device__ __forceinline__ void cp_commit() {
    asm volatile("cp.async.commit_group;\n" ::: "memory");
}
template <int N>
__device__ __forceinline__ void cp_wait() {
    asm volatile("cp.async.wait_group %0;\n" :: "n"(N) : "memory");
}

extern "C" __global__ void __launch_bounds__(THREADS, 2)
qc_hmma11_kernel(const float* __restrict__ x,  const float* __restrict__ W1,
                 const float* __restrict__ b1, const float* __restrict__ W2,
                 const float* __restrict__ b2, const float* __restrict__ qw,
                 float* __restrict__ out)
{
    extern __shared__ char sm[];
    const uint32_t sb = (uint32_t)__cvta_generic_to_shared(sm);
    const int t   = threadIdx.x;
    const int wid = t >> 5;
    const int lid = t & 31;
    const long row0 = (long)blockIdx.x * TM;

    float* b1s = (float*)(sm + OFF_B1);
    float* b2s = (float*)(sm + OFF_B2);
    float* cw  = (float*)(sm + OFF_CW);
    float* sw  = (float*)(sm + OFF_SW);
    float* W2t = (float*)(sm + OFF_W2T);

    // ---- per-warp async x pipeline: issue BEFORE prologue to hide it ----
    const uint32_t warpA = sb + OFF_A + (uint32_t)wid * AWREG;
    const float* xwarp = x + (row0 + wid * 32) * KD;
    auto cp_chunk = [&](int ch, int buf) {
        #pragma unroll
        for (int i = 0; i < 8; ++i) {
            int s   = lid + 32 * i;      // [0,256): 32 rows x 8 segs
            int r   = s >> 3;
            int seg = s & 7;
            cp_async16(warpA + (uint32_t)buf * AWBUF + (uint32_t)r * AROW + (uint32_t)seg * 16,
                       xwarp + r * KD + ch * KC + seg * 4);
        }
        cp_commit();
    };

    cp_chunk(0, 0);
    cp_chunk(1, 1);

    // ---- small tables + W1 prologue (overlaps in-flight x loads) ----
    if (t < 64)  b1s[t] = b1[t];
    if (t < 4)   b2s[t] = b2[t];
    if (t < 16)  sincosf(0.5f * qw[t], &sw[t], &cw[t]);
    { int j = t >> 6, q = t & 63; W2t[q * 4 + j] = W2[t]; }

    #pragma unroll
    for (int i = 0; i < 16; ++i) {
        int idx = t + i * THREADS;
        int row = idx >> 6;
        int k4  = idx & 63;
        float4 v = *(const float4*)(W1 + row * KD + k4 * 4);
        uint32_t o = (uint32_t)row * (BS * 2) + (uint32_t)k4 * 8;
        *(uint2*)(sm + OFF_B + o) = make_uint2(packh2(v.x, v.y), packh2(v.z, v.w));
    }
    __syncthreads();   // ONLY CTA barrier: B + tables visible

    float acc[16][4];
    #pragma unroll
    for (int ni = 0; ni < 16; ++ni)
        #pragma unroll
        for (int c = 0; c < 4; ++c) acc[ni][c] = 0.0f;

    const uint32_t aTh = (uint32_t)(lid >> 2) * AROW + (uint32_t)(lid & 3) * 8;
    const uint32_t bBase = sb + OFF_B
        + ((((uint32_t)lid >> 4) << 3) + ((uint32_t)lid & 7)) * (BS * 2)
        + (((uint32_t)lid >> 3) & 1) * 16;

    for (int ch = 0; ch < NCH; ++ch) {
        if (ch < NCH - 1) cp_wait<1>(); else cp_wait<0>();
        __syncwarp();

        const int buf = ch & 1;
        const char* aB = sm + OFF_A + wid * AWREG + buf * AWBUF;

        #pragma unroll
        for (int ks = 0; ks < 2; ++ks) {
            uint32_t a[2][4];
            #pragma unroll
            for (int h = 0; h < 2; ++h) {
                const char* ap = aB + aTh + h * 16 * AROW + ks * 64;
                float2 f0 = *(const float2*)(ap);
                float2 f1 = *(const float2*)(ap + 8 * AROW);
                float2 f2 = *(const float2*)(ap + 32);
                float2 f3 = *(const float2*)(ap + 8 * AROW + 32);
                a[h][0] = packh2(f0.x, f0.y);  a[h][1] = packh2(f1.x, f1.y);
                a[h][2] = packh2(f2.x, f2.y);  a[h][3] = packh2(f3.x, f3.y);
            }

            const int it = ch * 2 + ks;
            uint32_t bf[4][4];
            #pragma unroll
            for (int g = 0; g < 4; ++g)
                ldm_x4(bf[g][0], bf[g][1], bf[g][2], bf[g][3],
                       bBase + (uint32_t)g * 16 * (BS * 2) + (uint32_t)it * 32);

            #pragma unroll
            for (int g = 0; g < 4; ++g) {
                mma_f16(acc[g * 2],         a[0], bf[g][0], bf[g][1]);
                mma_f16(acc[g * 2 + 1],     a[0], bf[g][2], bf[g][3]);
                mma_f16(acc[8 + g * 2],     a[1], bf[g][0], bf[g][1]);
                mma_f16(acc[8 + g * 2 + 1], a[1], bf[g][2], bf[g][3]);
            }
        }

        if (ch + 2 < NCH) cp_chunk(ch + 2, buf);
    }

    // ---- stage H into own warp's A region; warp-local only -> no CTA barrier ----
    {
        char* hw = sm + OFF_A + wid * AWREG;    // 32 rows x 272 B
        int rloc = lid >> 2;
        int col0 = (lid & 3) * 2;
        #pragma unroll
        for (int h = 0; h < 2; ++h)
            #pragma unroll
            for (int ni = 0; ni < 8; ++ni) {
                int col = ni * 8 + col0;
                float* r0p = (float*)(hw + (h * 16 + rloc) * 272);
                float* r1p = (float*)(hw + (h * 16 + rloc + 8) * 272);
                *(float2*)(r0p + col) = make_float2(acc[h * 8 + ni][0], acc[h * 8 + ni][1]);
                *(float2*)(r1p + col) = make_float2(acc[h * 8 + ni][2], acc[h * 8 + ni][3]);
            }
    }
    __syncwarp();   // reader thread t consumes its OWN warp's rows

    // ---- per-row epilogue: all 256 threads, one row each (own warp region) ----
    {
        const float* hrow = (const float*)(sm + OFF_A + (t >> 5) * AWREG + (t & 31) * 272);
        float ang0 = b2s[0], ang1 = b2s[1], ang2 = b2s[2], ang3 = b2s[3];
        #pragma unroll
        for (int q4 = 0; q4 < 16; ++q4) {
            float4 h4 = *(const float4*)(hrow + q4 * 4);
            float4 bb = *(const float4*)(b1s + q4 * 4);
            #pragma unroll
            for (int i = 0; i < 4; ++i) {
                float hv = (i == 0) ? h4.x : (i == 1) ? h4.y : (i == 2) ? h4.z : h4.w;
                float bv = (i == 0) ? bb.x : (i == 1) ? bb.y : (i == 2) ? bb.z : bb.w;
                float hq = fmaxf(hv + bv, 0.0f);
                float4 w = *(const float4*)(W2t + (q4 * 4 + i) * 4);
                ang0 += hq * w.x;  ang1 += hq * w.y;
                ang2 += hq * w.z;  ang3 += hq * w.w;
            }
        }
        float ang[4] = { tanhf(ang0), tanhf(ang1), tanhf(ang2), tanhf(ang3) };

        float sr[16], si[16];
        #pragma unroll
        for (int i = 0; i < 16; ++i) { sr[i] = 0.0f; si[i] = 0.0f; }
        sr[0] = 1.0f;

        #pragma unroll
        for (int w = 0; w < 4; ++w) {
            float c, s;
            __sincosf(0.5f * ang[w], &s, &c);
            const int m = 8 >> w;
            #pragma unroll
            for (int i0 = 0; i0 < 16; ++i0) if (!(i0 & m)) {
                const int i1 = i0 | m;
                float r0 = sr[i0], r1 = sr[i1];
                sr[i0] = c * r0 - s * r1;  sr[i1] = s * r0 + c * r1;
                float q0 = si[i0], q1 = si[i1];
                si[i0] = c * q0 - s * q1;  si[i1] = s * q0 + c * q1;
            }
        }

        #pragma unroll
        for (int l = 0; l < 2; ++l) {
            #pragma unroll
            for (int i = 0; i < 4; ++i) {
                {   // RY(weights[l,i,0])
                    const float c = cw[l * 8 + i * 2], s = sw[l * 8 + i * 2];
                    const int m = 8 >> i;
                    #pragma unroll
                    for (int i0 = 0; i0 < 16; ++i0) if (!(i0 & m)) {
                        const int i1 = i0 | m;
                        float r0 = sr[i0], r1 = sr[i1];
                        sr[i0] = c * r0 - s * r1;  sr[i1] = s * r0 + c * r1;
                        float q0 = si[i0], q1 = si[i1];
                        si[i0] = c * q0 - s * q1;  si[i1] = s * q0 + c * q1;
                    }
                }
                {   // RZ(weights[l,i,1])
                    const float c = cw[l * 8 + i * 2 + 1], s = sw[l * 8 + i * 2 + 1];
                    const int m = 8 >> i;
                    #pragma unroll
                    for (int idx = 0; idx < 16; ++idx) {
                        float re = sr[idx], im = si[idx];
                        if (idx & m) { sr[idx] = re * c - im * s;  si[idx] = im * c + re * s; }
                        else         { sr[idx] = re * c + im * s;  si[idx] = im * c - re * s; }
                    }
                }
            }
            #pragma unroll
            for (int cix = 0; cix < 4; ++cix) {
                const int ctrl = cix, tgt = (cix + 1) & 3;
                const int mc = 8 >> ctrl, mt = 8 >> tgt;
                #pragma unroll
                for (int idx = 0; idx < 16; ++idx)
                    if ((idx & mc) && !(idx & mt)) {
                        const int j2 = idx | mt;
                        float tr = sr[idx]; sr[idx] = sr[j2]; sr[j2] = tr;
                        float ti = si[idx]; si[idx] = si[j2]; si[j2] = ti;
                    }
            }
        }

        float z = 0.0f;
        #pragma unroll
        for (int idx = 0; idx < 16; ++idx) {
            float p = sr[idx] * sr[idx] + si[idx] * si[idx];
            z += (idx & 8) ? -p : p;
        }
        out[row0 + t] = z;
    }
}

extern "C" void kernel_launch(void* const* d_in, const int* in_sizes, int n_in,
                              void* d_out, int out_size) {
    const float* x  = (const float*)d_in[0];
    const float* W1 = (const float*)d_in[1];
    const float* b1 = (const float*)d_in[2];
    const float* W2 = (const float*)d_in[3];
    const float* b2 = (const float*)d_in[4];
    const float* qw = (const float*)d_in[5];
    float* out = (float*)d_out;

    const int B = in_sizes[0] / KD;   // 65536
    cudaFuncSetAttribute(qc_hmma11_kernel,
                         cudaFuncAttributeMaxDynamicSharedMemorySize, SMEM_BYTES);
    qc_hmma11_kernel<<<B / TM, THREADS, SMEM_BYTES>>>(x, W1, b1, W2, b2, qw, out);
}